// round 8
// baseline (speedup 1.0000x reference)
#include <cuda_runtime.h>
#include <cuda_bf16.h>
#include <math.h>

#define DIM   256
#define TSEQ  4096
#define BATCH 32
#define HD    64
#define MTOT  (BATCH * TSEQ)   // 131072

// ---------------- device scratch ----------------
__device__ float g_q[(size_t)MTOT * DIM];
__device__ float g_k[(size_t)MTOT * DIM];
__device__ float g_v[(size_t)MTOT * DIM];
__device__ __nv_bfloat16 g_wh[3][DIM * DIM];
__device__ __nv_bfloat16 g_wl[3][DIM * DIM];
__device__ float g_acc[BATCH * DIM];

__global__ void zero_acc_kernel() {
    int i = blockIdx.x * blockDim.x + threadIdx.x;
    if (i < BATCH * DIM) g_acc[i] = 0.0f;
}

// ---------------- asm helpers ----------------
__device__ __forceinline__ void cp_async16(unsigned dst, const void* src) {
    asm volatile("cp.async.cg.shared.global [%0], [%1], 16;" :: "r"(dst), "l"(src));
}
__device__ __forceinline__ void cp_commit() { asm volatile("cp.async.commit_group;"); }
__device__ __forceinline__ void cp_wait1() { asm volatile("cp.async.wait_group 1;"); }
__device__ __forceinline__ void cp_wait0() { asm volatile("cp.async.wait_group 0;"); }
__device__ __forceinline__ void ldsm_x4(unsigned& r0, unsigned& r1, unsigned& r2, unsigned& r3,
                                        unsigned addr) {
    asm volatile("ldmatrix.sync.aligned.m8n8.x4.shared.b16 {%0,%1,%2,%3},[%4];"
                 : "=r"(r0), "=r"(r1), "=r"(r2), "=r"(r3) : "r"(addr));
}
__device__ __forceinline__ void ldsm_x4_trans(unsigned& r0, unsigned& r1, unsigned& r2, unsigned& r3,
                                              unsigned addr) {
    asm volatile("ldmatrix.sync.aligned.m8n8.x4.trans.shared.b16 {%0,%1,%2,%3},[%4];"
                 : "=r"(r0), "=r"(r1), "=r"(r2), "=r"(r3) : "r"(addr));
}
__device__ __forceinline__ void mma_bf16(float* D, unsigned a0, unsigned a1, unsigned a2, unsigned a3,
                                         unsigned b0, unsigned b1) {
    asm volatile("mma.sync.aligned.m16n8k16.row.col.f32.bf16.bf16.f32 "
                 "{%0,%1,%2,%3},{%4,%5,%6,%7},{%8,%9},{%0,%1,%2,%3};"
                 : "+f"(D[0]), "+f"(D[1]), "+f"(D[2]), "+f"(D[3])
                 : "r"(a0), "r"(a1), "r"(a2), "r"(a3), "r"(b0), "r"(b1));
}

// ---------------- W hi/lo split ----------------
__global__ __launch_bounds__(256) void cvt_w_kernel(const float* __restrict__ Wq,
                                                    const float* __restrict__ Wk,
                                                    const float* __restrict__ Wv) {
    int i = (blockIdx.x * 256 + threadIdx.x) * 4;
    if (i >= 3 * DIM * DIM) return;
    int z = i >> 16;
    int o = i & 65535;
    const float* W = (z == 0) ? Wq : (z == 1) ? Wk : Wv;
    float4 v = *(const float4*)(W + o);
    float f[4] = {v.x, v.y, v.z, v.w};
    unsigned short hs[4], ls[4];
    #pragma unroll
    for (int j = 0; j < 4; j++) {
        __nv_bfloat16 h = __float2bfloat16(f[j]);
        float hf = __bfloat162float(h);
        __nv_bfloat16 l = __float2bfloat16(f[j] - hf);
        hs[j] = __bfloat16_as_ushort(h);
        ls[j] = __bfloat16_as_ushort(l);
    }
    uint2 ph, pl;
    ph.x = (unsigned)hs[0] | ((unsigned)hs[1] << 16);
    ph.y = (unsigned)hs[2] | ((unsigned)hs[3] << 16);
    pl.x = (unsigned)ls[0] | ((unsigned)ls[1] << 16);
    pl.y = (unsigned)ls[2] | ((unsigned)ls[3] << 16);
    *(uint2*)(&g_wh[z][o]) = ph;
    *(uint2*)(&g_wl[z][o]) = pl;
}

// ---------------- fused convert + tensor-core GEMM (unchanged from R7) ----------------
#define ASTRIDE 72
#define WSTRIDE 136
#define AH_OFF 0
#define AL_OFF 9216
#define W_OFF  18432
#define W_STAGE 17408
#define W_HL    8704
#define GSMEM_BYTES ((18432 + 2 * 17408) * 2)   // 106496

__device__ __forceinline__ void g_load_w(int c, int buf, int tid, int nbase,
                                         const __nv_bfloat16* Whz,
                                         const __nv_bfloat16* Wlz,
                                         unsigned sb)
{
    #pragma unroll
    for (int hl = 0; hl < 2; hl++) {
        const __nv_bfloat16* W = hl ? Wlz : Whz;
        unsigned base = sb + (unsigned)(W_OFF + buf * W_STAGE + hl * W_HL) * 2u;
        #pragma unroll
        for (int i = 0; i < 4; i++) {
            int lin = tid + i * 256;
            int r = lin >> 4, c8 = lin & 15;
            cp_async16(base + (unsigned)(r * WSTRIDE + c8 * 8) * 2u,
                       (const void*)(W + (c * 64 + r) * DIM + nbase + c8 * 8));
        }
    }
    cp_commit();
}

__global__ __launch_bounds__(256, 2) void gemm_fused_kernel(
    const float* __restrict__ x,
    const float* __restrict__ bq, const float* __restrict__ bk, const float* __restrict__ bv)
{
    extern __shared__ __nv_bfloat16 sm[];
    const unsigned sb = (unsigned)__cvta_generic_to_shared(sm);

    const int z = blockIdx.x;
    const int nbase = blockIdx.y * 128;
    const long mbase = (long)blockIdx.z * 128;
    const float* bias = (z == 0) ? bq : (z == 1) ? bk : bv;
    float* C = (z == 0) ? g_q : (z == 1) ? g_k : g_v;
    const __nv_bfloat16* Whz = g_wh[z];
    const __nv_bfloat16* Wlz = g_wl[z];

    const int tid = threadIdx.x;
    const int warp = tid >> 5, lane = tid & 31;
    const int wm = (warp >> 1) * 32;
    const int wn = (warp & 1) * 64;

    float acc[2][8][4];
    #pragma unroll
    for (int i = 0; i < 2; i++)
        #pragma unroll
        for (int j = 0; j < 8; j++)
            #pragma unroll
            for (int c = 0; c < 4; c++) acc[i][j][c] = 0.0f;

    g_load_w(0, 0, tid, nbase, Whz, Wlz, sb);
    g_load_w(1, 1, tid, nbase, Whz, Wlz, sb);

    for (int c = 0; c < 4; c++) {
        const int buf = c & 1;

        #pragma unroll
        for (int i = 0; i < 8; i++) {
            int lin = tid + i * 256;
            int r = lin >> 4, c4 = lin & 15;
            float4 v = *(const float4*)(x + (mbase + r) * DIM + c * 64 + c4 * 4);
            float f[4] = {v.x, v.y, v.z, v.w};
            unsigned short hs[4], ls[4];
            #pragma unroll
            for (int j = 0; j < 4; j++) {
                __nv_bfloat16 h = __float2bfloat16(f[j]);
                float hf = __bfloat162float(h);
                __nv_bfloat16 l = __float2bfloat16(f[j] - hf);
                hs[j] = __bfloat16_as_ushort(h);
                ls[j] = __bfloat16_as_ushort(l);
            }
            uint2 ph, pl;
            ph.x = (unsigned)hs[0] | ((unsigned)hs[1] << 16);
            ph.y = (unsigned)hs[2] | ((unsigned)hs[3] << 16);
            pl.x = (unsigned)ls[0] | ((unsigned)ls[1] << 16);
            pl.y = (unsigned)ls[2] | ((unsigned)ls[3] << 16);
            *(uint2*)(sm + AH_OFF + r * ASTRIDE + c4 * 4) = ph;
            *(uint2*)(sm + AL_OFF + r * ASTRIDE + c4 * 4) = pl;
        }

        if (c < 3) cp_wait1(); else cp_wait0();
        __syncthreads();

        const unsigned ah_base = sb + (unsigned)AH_OFF * 2u;
        const unsigned al_base = sb + (unsigned)AL_OFF * 2u;
        const unsigned wh_base = sb + (unsigned)(W_OFF + buf * W_STAGE) * 2u;
        const unsigned wl_base = wh_base + (unsigned)W_HL * 2u;

        #pragma unroll
        for (int kk = 0; kk < 4; kk++) {
            const unsigned arow = (unsigned)((wm + (lane & 15)) * ASTRIDE + kk * 16 + (lane >> 4) * 8) * 2u;
            unsigned ah[2][4], al[2][4];
            ldsm_x4(ah[0][0], ah[0][1], ah[0][2], ah[0][3], ah_base + arow);
            ldsm_x4(ah[1][0], ah[1][1], ah[1][2], ah[1][3], ah_base + arow + (unsigned)(16 * ASTRIDE) * 2u);
            ldsm_x4(al[0][0], al[0][1], al[0][2], al[0][3], al_base + arow);
            ldsm_x4(al[1][0], al[1][1], al[1][2], al[1][3], al_base + arow + (unsigned)(16 * ASTRIDE) * 2u);

            #pragma unroll
            for (int nt = 0; nt < 4; nt++) {
                const unsigned boff =
                    (unsigned)((kk * 16 + (lane & 15)) * WSTRIDE + wn + nt * 16 + (lane >> 4) * 8) * 2u;
                unsigned h0, h1, h2, h3, l0, l1, l2, l3;
                ldsm_x4_trans(h0, h1, h2, h3, wh_base + boff);
                ldsm_x4_trans(l0, l1, l2, l3, wl_base + boff);
                #pragma unroll
                for (int mi = 0; mi < 2; mi++) {
                    mma_bf16(acc[mi][nt * 2],     ah[mi][0], ah[mi][1], ah[mi][2], ah[mi][3], h0, h1);
                    mma_bf16(acc[mi][nt * 2 + 1], ah[mi][0], ah[mi][1], ah[mi][2], ah[mi][3], h2, h3);
                    mma_bf16(acc[mi][nt * 2],     ah[mi][0], ah[mi][1], ah[mi][2], ah[mi][3], l0, l1);
                    mma_bf16(acc[mi][nt * 2 + 1], ah[mi][0], ah[mi][1], ah[mi][2], ah[mi][3], l2, l3);
                    mma_bf16(acc[mi][nt * 2],     al[mi][0], al[mi][1], al[mi][2], al[mi][3], h0, h1);
                    mma_bf16(acc[mi][nt * 2 + 1], al[mi][0], al[mi][1], al[mi][2], al[mi][3], h2, h3);
                }
            }
        }
        __syncthreads();
        if (c + 2 <= 3) g_load_w(c + 2, buf, tid, nbase, Whz, Wlz, sb);
    }

    #pragma unroll
    for (int mi = 0; mi < 2; mi++) {
        long row0 = mbase + wm + mi * 16 + (lane >> 2);
        #pragma unroll
        for (int n8 = 0; n8 < 8; n8++) {
            int col = nbase + wn + n8 * 8 + (lane & 3) * 2;
            float b0 = __ldg(&bias[col]);
            float b1 = __ldg(&bias[col + 1]);
            float2 o0, o1;
            o0.x = acc[mi][n8][0] + b0;
            o0.y = acc[mi][n8][1] + b1;
            o1.x = acc[mi][n8][2] + b0;
            o1.y = acc[mi][n8][3] + b1;
            *(float2*)&C[row0 * DIM + col] = o0;
            *(float2*)&C[(row0 + 8) * DIM + col] = o1;
        }
    }
}

// ---------------- attention: pooled tiles + vectorized, span=32 ----------------
#define ASTR   68      // floats per row (16B aligned)
#define NBROWS 35      // base rows: orig sbase..sbase+34 (halo 3 for pooling)
#define NPROWS 24      // pooled rows: 16 (scale2) + 8 (scale4)

// phase A: single-row dot products, float4
__device__ __forceinline__ void scores_v(const float* __restrict__ qt,
                                         const float* __restrict__ kt,
                                         int lrow, int lk0,
                                         float* __restrict__ aout,
                                         int l0, int lq, int Ts)
{
    const float4* qp = (const float4*)(qt + lrow * ASTR);
    const float4* k0 = (const float4*)(kt + lk0 * ASTR);
    const float4* k1 = k0 + 17;
    const float4* k2 = k1 + 17;
    const float4* k3 = k2 + 17;
    float s0 = 0.f, s1 = 0.f, s2 = 0.f, s3 = 0.f;
    #pragma unroll
    for (int c = 0; c < 16; c++) {
        float4 q4 = qp[c];
        float4 a = k0[c], b = k1[c], d = k2[c], e = k3[c];
        s0 += q4.x * a.x + q4.y * a.y + q4.z * a.z + q4.w * a.w;
        s1 += q4.x * b.x + q4.y * b.y + q4.z * b.z + q4.w * b.w;
        s2 += q4.x * d.x + q4.y * d.y + q4.z * d.z + q4.w * d.w;
        s3 += q4.x * e.x + q4.y * e.y + q4.z * e.z + q4.w * e.w;
    }
    bool v0 = l0 < Ts, v1 = l0 + 1 < Ts, v2 = l0 + 2 < Ts, v3 = l0 + 3 < Ts;
    s0 = v0 ? s0 * 0.125f : 0.f;
    s1 = v1 ? s1 * 0.125f : 0.f;
    s2 = v2 ? s2 * 0.125f : 0.f;
    s3 = v3 ? s3 * 0.125f : 0.f;
    float mx = fmaxf(fmaxf(s0, s1), fmaxf(s2, s3));
    float e0 = expf(s0 - mx), e1 = expf(s1 - mx);
    float e2 = expf(s2 - mx), e3 = expf(s3 - mx);
    float inv = 1.0f / (e0 + e1 + e2 + e3);
    aout[0] = v0 ? e0 * inv : 0.f;
    aout[1] = v1 ? e1 * inv : 0.f;
    aout[2] = v2 ? e2 * inv : 0.f;
    aout[3] = v3 ? e3 * inv : 0.f;
    float wgt = 0.f;
    if (lq < Ts)
        wgt = (float)((TSEQ * (lq + 1) + Ts - 1) / Ts - (TSEQ * lq + Ts - 1) / Ts);
    aout[4] = wgt;
}

// phase B: lane owns dims (2*lane, 2*lane+1), float2 v loads
__device__ __forceinline__ void outrows_v(const float* __restrict__ vt,
                                          const float* __restrict__ awb,
                                          int r0, int r1, int voff, int lane,
                                          float& acc0, float& acc1)
{
    const float2* vbase = (const float2*)vt + lane;
    for (int rl = r0; rl < r1; rl++) {
        const float* e = awb + rl * 8;
        float wgt = e[4];
        if (wgt == 0.0f) continue;
        const float2* vp = vbase + (voff + (rl >> 2) * 4) * 34;
        float2 w0 = vp[0], w1 = vp[34], w2 = vp[68], w3 = vp[102];
        float a0 = e[0], a1 = e[1], a2 = e[2], a3 = e[3];
        float o0 = a0 * w0.x + a1 * w1.x + a2 * w2.x + a3 * w3.x;
        float o1 = a0 * w0.y + a1 * w1.y + a2 * w2.y + a3 * w3.y;
        float g0 = 0.5f * o0 * (1.0f + erff(o0 * 0.70710678118f));
        float g1 = 0.5f * o1 * (1.0f + erff(o1 * 0.70710678118f));
        acc0 += wgt * g0;
        acc1 += wgt * g1;
    }
}

__global__ __launch_bounds__(128) void attn4_kernel()
{
    extern __shared__ float smf[];
    float* bq_ = smf;                                   // base q [35][68]
    float* bk_ = bq_ + NBROWS * ASTR;
    float* bv_ = bk_ + NBROWS * ASTR;
    float* pq  = bv_ + NBROWS * ASTR;                   // pooled q [24][68]
    float* pk  = pq + NPROWS * ASTR;
    float* pv  = pk + NPROWS * ASTR;
    float* aw  = pv + NPROWS * ASTR;                    // [56][8]
    float* accw = aw + 56 * 8;                          // [4][64]

    const int tid = threadIdx.x;
    const int h  = blockIdx.x;
    const int bi = blockIdx.y;     // span 0..128 (128 = ragged tail)
    const int b  = blockIdx.z;
    const int sbase = bi * 32 - 3;
    const long gbase = (long)b * TSEQ * DIM + h * HD;

    const float* gq = g_q + gbase;
    const float* gk = g_k + gbase;
    const float* gv = g_v + gbase;

    // stage base tiles (reflect at global edges)
    for (int idx = tid; idx < 3 * NBROWS * 16; idx += 128) {
        int t = idx / (NBROWS * 16);
        int rem = idx - t * (NBROWS * 16);
        int r = rem >> 4;
        int c4 = (rem & 15) * 4;
        int o = sbase + r;
        if (o < 0) o = -o;
        if (o >= TSEQ) o = 2 * TSEQ - 2 - o;
        const float* src = (t == 0 ? gq : t == 1 ? gk : gv) + (long)o * DIM + c4;
        float4 v = *(const float4*)src;
        float* dst = (t == 0 ? bq_ : t == 1 ? bk_ : bv_) + r * ASTR + c4;
        *(float4*)dst = v;
    }
    __syncthreads();

    // pooling pass: rows 0-15 = scale2 (avg of base rows 2l+2,2l+3),
    //               rows 16-23 = scale4 (avg of base rows 4l+1..4l+4)
    for (int idx = tid; idx < 3 * NPROWS * 16; idx += 128) {
        int t = idx / (NPROWS * 16);
        int rem = idx - t * (NPROWS * 16);
        int r = rem >> 4;
        int c4 = (rem & 15) * 4;
        const float* bt = (t == 0 ? bq_ : t == 1 ? bk_ : bv_);
        float* pt = (t == 0 ? pq : t == 1 ? pk : pv);
        float4 o;
        if (r < 16) {
            const float4 a = *(const float4*)(bt + (2 * r + 2) * ASTR + c4);
            const float4 c = *(const float4*)(bt + (2 * r + 3) * ASTR + c4);
            o.x = 0.5f * (a.x + c.x); o.y = 0.5f * (a.y + c.y);
            o.z = 0.5f * (a.z + c.z); o.w = 0.5f * (a.w + c.w);
        } else {
            int rr = r - 16;
            const float4 a = *(const float4*)(bt + (4 * rr + 1) * ASTR + c4);
            const float4 c = *(const float4*)(bt + (4 * rr + 2) * ASTR + c4);
            const float4 d = *(const float4*)(bt + (4 * rr + 3) * ASTR + c4);
            const float4 e = *(const float4*)(bt + (4 * rr + 4) * ASTR + c4);
            o.x = 0.25f * (a.x + c.x + d.x + e.x);
            o.y = 0.25f * (a.y + c.y + d.y + e.y);
            o.z = 0.25f * (a.z + c.z + d.z + e.z);
            o.w = 0.25f * (a.w + c.w + d.w + e.w);
        }
        *(float4*)(pt + r * ASTR + c4) = o;
    }
    __syncthreads();

    const int warp = tid >> 5;
    const int lane = tid & 31;

    // phase A
    if (warp == 0) {
        int wl = lane >> 2;
        int l0 = bi * 32 + wl * 4;
        scores_v(bq_, bk_, 3 + lane, 3 + wl * 4, aw + lane * 8, l0, bi * 32 + lane, TSEQ);
    } else if (warp == 1) {
        if (lane < 16) {
            int wl = lane >> 2;
            int l0 = bi * 16 + wl * 4;
            scores_v(pq, pk, lane, wl * 4, aw + (32 + lane) * 8, l0, bi * 16 + lane, 2049);
        } else if (lane < 24) {
            int ll = lane - 16;
            int wl = ll >> 2;
            int l0 = bi * 8 + wl * 4;
            scores_v(pq, pk, 16 + ll, 16 + wl * 4, aw + (48 + ll) * 8, l0, bi * 8 + ll, 1025);
        }
    }
    __syncthreads();

    // phase B
    float acc0 = 0.f, acc1 = 0.f;
    if (warp == 0)      outrows_v(bv_, aw,          0, 16, 3,  lane, acc0, acc1);
    else if (warp == 2) outrows_v(bv_, aw,         16, 32, 3,  lane, acc0, acc1);
    else if (warp == 1) outrows_v(pv,  aw + 32 * 8, 0, 16, 0,  lane, acc0, acc1);
    else                outrows_v(pv,  aw + 48 * 8, 0,  8, 16, lane, acc0, acc1);

    *(float2*)&accw[warp * HD + 2 * lane] = make_float2(acc0, acc1);
    __syncthreads();

    if (tid < HD) {
        float s = accw[tid] + accw[HD + tid] + accw[2 * HD + tid] + accw[3 * HD + tid];
        atomicAdd(&g_acc[b * DIM + h * HD + tid], s);
    }
}

// ---------------- classifier ----------------
__global__ __launch_bounds__(256) void classifier_kernel(
    const float* __restrict__ Wp,  const float* __restrict__ bp,
    const float* __restrict__ Wc1, const float* __restrict__ bc1,
    const float* __restrict__ Wc2, const float* __restrict__ bc2,
    float* __restrict__ out)
{
    __shared__ float m[DIM], fm[DIM], hbuf[DIM];
    const int b = blockIdx.x;
    const int t = threadIdx.x;

    m[t] = g_acc[b * DIM + t] * (1.0f / (float)TSEQ);
    __syncthreads();

    float a = bp[t];
    for (int k = 0; k < DIM; k++) a += m[k] * Wp[k * DIM + t];
    fm[t] = a;
    __syncthreads();

    float a2 = bc1[t];
    for (int k = 0; k < DIM; k++) a2 += fm[k] * Wc1[k * DIM + t];
    hbuf[t] = fmaxf(a2, 0.0f);
    __syncthreads();

    if (t < 7) {
        float a3 = bc2[t];
        for (int k = 0; k < DIM; k++) a3 += hbuf[k] * Wc2[k * 7 + t];
        out[b * 7 + t] = a3;
    }
}

// ---------------- launch ----------------
extern "C" void kernel_launch(void* const* d_in, const int* in_sizes, int n_in,
                              void* d_out, int out_size)
{
    const float* x   = (const float*)d_in[0];
    const float* Wq  = (const float*)d_in[1];
    const float* bq  = (const float*)d_in[2];
    const float* Wk  = (const float*)d_in[3];
    const float* bk  = (const float*)d_in[4];
    const float* Wv  = (const float*)d_in[5];
    const float* bv  = (const float*)d_in[6];
    const float* Wp  = (const float*)d_in[7];
    const float* bp  = (const float*)d_in[8];
    const float* Wc1 = (const float*)d_in[9];
    const float* bc1 = (const float*)d_in[10];
    const float* Wc2 = (const float*)d_in[11];
    const float* bc2 = (const float*)d_in[12];
    float* out = (float*)d_out;

    const int asmem = (3 * NBROWS * ASTR + 3 * NPROWS * ASTR + 56 * 8 + 4 * HD) * (int)sizeof(float);
    cudaFuncSetAttribute(gemm_fused_kernel, cudaFuncAttributeMaxDynamicSharedMemorySize, GSMEM_BYTES);
    cudaFuncSetAttribute(attn4_kernel, cudaFuncAttributeMaxDynamicSharedMemorySize, asmem);

    zero_acc_kernel<<<(BATCH * DIM + 255) / 256, 256>>>();

    cvt_w_kernel<<<(3 * DIM * DIM / 4 + 255) / 256, 256>>>(Wq, Wk, Wv);

    gemm_fused_kernel<<<dim3(3, 2, MTOT / 128), 256, GSMEM_BYTES>>>(x, bq, bk, bv);

    attn4_kernel<<<dim3(4, 129, BATCH), 128, asmem>>>();

    classifier_kernel<<<BATCH, 256>>>(Wp, bp, Wc1, bc1, Wc2, bc2, out);
}

// round 9
// speedup vs baseline: 1.1941x; 1.1941x over previous
#include <cuda_runtime.h>
#include <cuda_bf16.h>
#include <math.h>

#define DIM   256
#define TSEQ  4096
#define BATCH 32
#define HD    64
#define MTOT  (BATCH * TSEQ)   // 131072

// ---------------- device scratch ----------------
__device__ float g_q[(size_t)MTOT * DIM];
__device__ float g_k[(size_t)MTOT * DIM];
__device__ float g_v[(size_t)MTOT * DIM];
__device__ __nv_bfloat16 g_wh[3][DIM * DIM];
__device__ __nv_bfloat16 g_wl[3][DIM * DIM];
__device__ float g_acc[BATCH * DIM];

__global__ void zero_acc_kernel() {
    int i = blockIdx.x * blockDim.x + threadIdx.x;
    if (i < BATCH * DIM) g_acc[i] = 0.0f;
}

// ---------------- asm helpers ----------------
__device__ __forceinline__ void cp_async16(unsigned dst, const void* src) {
    asm volatile("cp.async.cg.shared.global [%0], [%1], 16;" :: "r"(dst), "l"(src));
}
__device__ __forceinline__ void cp_commit() { asm volatile("cp.async.commit_group;"); }
__device__ __forceinline__ void cp_wait1() { asm volatile("cp.async.wait_group 1;"); }
__device__ __forceinline__ void cp_wait0() { asm volatile("cp.async.wait_group 0;"); }
__device__ __forceinline__ void ldsm_x4(unsigned& r0, unsigned& r1, unsigned& r2, unsigned& r3,
                                        unsigned addr) {
    asm volatile("ldmatrix.sync.aligned.m8n8.x4.shared.b16 {%0,%1,%2,%3},[%4];"
                 : "=r"(r0), "=r"(r1), "=r"(r2), "=r"(r3) : "r"(addr));
}
__device__ __forceinline__ void ldsm_x4_trans(unsigned& r0, unsigned& r1, unsigned& r2, unsigned& r3,
                                              unsigned addr) {
    asm volatile("ldmatrix.sync.aligned.m8n8.x4.trans.shared.b16 {%0,%1,%2,%3},[%4];"
                 : "=r"(r0), "=r"(r1), "=r"(r2), "=r"(r3) : "r"(addr));
}
__device__ __forceinline__ void mma_bf16(float* D, unsigned a0, unsigned a1, unsigned a2, unsigned a3,
                                         unsigned b0, unsigned b1) {
    asm volatile("mma.sync.aligned.m16n8k16.row.col.f32.bf16.bf16.f32 "
                 "{%0,%1,%2,%3},{%4,%5,%6,%7},{%8,%9},{%0,%1,%2,%3};"
                 : "+f"(D[0]), "+f"(D[1]), "+f"(D[2]), "+f"(D[3])
                 : "r"(a0), "r"(a1), "r"(a2), "r"(a3), "r"(b0), "r"(b1));
}

// ---------------- W hi/lo split ----------------
__global__ __launch_bounds__(256) void cvt_w_kernel(const float* __restrict__ Wq,
                                                    const float* __restrict__ Wk,
                                                    const float* __restrict__ Wv) {
    int i = (blockIdx.x * 256 + threadIdx.x) * 4;
    if (i >= 3 * DIM * DIM) return;
    int z = i >> 16;
    int o = i & 65535;
    const float* W = (z == 0) ? Wq : (z == 1) ? Wk : Wv;
    float4 v = *(const float4*)(W + o);
    float f[4] = {v.x, v.y, v.z, v.w};
    unsigned short hs[4], ls[4];
    #pragma unroll
    for (int j = 0; j < 4; j++) {
        __nv_bfloat16 h = __float2bfloat16(f[j]);
        float hf = __bfloat162float(h);
        __nv_bfloat16 l = __float2bfloat16(f[j] - hf);
        hs[j] = __bfloat16_as_ushort(h);
        ls[j] = __bfloat16_as_ushort(l);
    }
    uint2 ph, pl;
    ph.x = (unsigned)hs[0] | ((unsigned)hs[1] << 16);
    ph.y = (unsigned)hs[2] | ((unsigned)hs[3] << 16);
    pl.x = (unsigned)ls[0] | ((unsigned)ls[1] << 16);
    pl.y = (unsigned)ls[2] | ((unsigned)ls[3] << 16);
    *(uint2*)(&g_wh[z][o]) = ph;
    *(uint2*)(&g_wl[z][o]) = pl;
}

// ---------------- fused convert + tensor-core GEMM (unchanged from R7) ----------------
#define ASTRIDE 72
#define WSTRIDE 136
#define AH_OFF 0
#define AL_OFF 9216
#define W_OFF  18432
#define W_STAGE 17408
#define W_HL    8704
#define GSMEM_BYTES ((18432 + 2 * 17408) * 2)   // 106496

__device__ __forceinline__ void g_load_w(int c, int buf, int tid, int nbase,
                                         const __nv_bfloat16* Whz,
                                         const __nv_bfloat16* Wlz,
                                         unsigned sb)
{
    #pragma unroll
    for (int hl = 0; hl < 2; hl++) {
        const __nv_bfloat16* W = hl ? Wlz : Whz;
        unsigned base = sb + (unsigned)(W_OFF + buf * W_STAGE + hl * W_HL) * 2u;
        #pragma unroll
        for (int i = 0; i < 4; i++) {
            int lin = tid + i * 256;
            int r = lin >> 4, c8 = lin & 15;
            cp_async16(base + (unsigned)(r * WSTRIDE + c8 * 8) * 2u,
                       (const void*)(W + (c * 64 + r) * DIM + nbase + c8 * 8));
        }
    }
    cp_commit();
}

__global__ __launch_bounds__(256, 2) void gemm_fused_kernel(
    const float* __restrict__ x,
    const float* __restrict__ bq, const float* __restrict__ bk, const float* __restrict__ bv)
{
    extern __shared__ __nv_bfloat16 sm[];
    const unsigned sb = (unsigned)__cvta_generic_to_shared(sm);

    const int z = blockIdx.x;
    const int nbase = blockIdx.y * 128;
    const long mbase = (long)blockIdx.z * 128;
    const float* bias = (z == 0) ? bq : (z == 1) ? bk : bv;
    float* C = (z == 0) ? g_q : (z == 1) ? g_k : g_v;
    const __nv_bfloat16* Whz = g_wh[z];
    const __nv_bfloat16* Wlz = g_wl[z];

    const int tid = threadIdx.x;
    const int warp = tid >> 5, lane = tid & 31;
    const int wm = (warp >> 1) * 32;
    const int wn = (warp & 1) * 64;

    float acc[2][8][4];
    #pragma unroll
    for (int i = 0; i < 2; i++)
        #pragma unroll
        for (int j = 0; j < 8; j++)
            #pragma unroll
            for (int c = 0; c < 4; c++) acc[i][j][c] = 0.0f;

    g_load_w(0, 0, tid, nbase, Whz, Wlz, sb);
    g_load_w(1, 1, tid, nbase, Whz, Wlz, sb);

    for (int c = 0; c < 4; c++) {
        const int buf = c & 1;

        #pragma unroll
        for (int i = 0; i < 8; i++) {
            int lin = tid + i * 256;
            int r = lin >> 4, c4 = lin & 15;
            float4 v = *(const float4*)(x + (mbase + r) * DIM + c * 64 + c4 * 4);
            float f[4] = {v.x, v.y, v.z, v.w};
            unsigned short hs[4], ls[4];
            #pragma unroll
            for (int j = 0; j < 4; j++) {
                __nv_bfloat16 h = __float2bfloat16(f[j]);
                float hf = __bfloat162float(h);
                __nv_bfloat16 l = __float2bfloat16(f[j] - hf);
                hs[j] = __bfloat16_as_ushort(h);
                ls[j] = __bfloat16_as_ushort(l);
            }
            uint2 ph, pl;
            ph.x = (unsigned)hs[0] | ((unsigned)hs[1] << 16);
            ph.y = (unsigned)hs[2] | ((unsigned)hs[3] << 16);
            pl.x = (unsigned)ls[0] | ((unsigned)ls[1] << 16);
            pl.y = (unsigned)ls[2] | ((unsigned)ls[3] << 16);
            *(uint2*)(sm + AH_OFF + r * ASTRIDE + c4 * 4) = ph;
            *(uint2*)(sm + AL_OFF + r * ASTRIDE + c4 * 4) = pl;
        }

        if (c < 3) cp_wait1(); else cp_wait0();
        __syncthreads();

        const unsigned ah_base = sb + (unsigned)AH_OFF * 2u;
        const unsigned al_base = sb + (unsigned)AL_OFF * 2u;
        const unsigned wh_base = sb + (unsigned)(W_OFF + buf * W_STAGE) * 2u;
        const unsigned wl_base = wh_base + (unsigned)W_HL * 2u;

        #pragma unroll
        for (int kk = 0; kk < 4; kk++) {
            const unsigned arow = (unsigned)((wm + (lane & 15)) * ASTRIDE + kk * 16 + (lane >> 4) * 8) * 2u;
            unsigned ah[2][4], al[2][4];
            ldsm_x4(ah[0][0], ah[0][1], ah[0][2], ah[0][3], ah_base + arow);
            ldsm_x4(ah[1][0], ah[1][1], ah[1][2], ah[1][3], ah_base + arow + (unsigned)(16 * ASTRIDE) * 2u);
            ldsm_x4(al[0][0], al[0][1], al[0][2], al[0][3], al_base + arow);
            ldsm_x4(al[1][0], al[1][1], al[1][2], al[1][3], al_base + arow + (unsigned)(16 * ASTRIDE) * 2u);

            #pragma unroll
            for (int nt = 0; nt < 4; nt++) {
                const unsigned boff =
                    (unsigned)((kk * 16 + (lane & 15)) * WSTRIDE + wn + nt * 16 + (lane >> 4) * 8) * 2u;
                unsigned h0, h1, h2, h3, l0, l1, l2, l3;
                ldsm_x4_trans(h0, h1, h2, h3, wh_base + boff);
                ldsm_x4_trans(l0, l1, l2, l3, wl_base + boff);
                #pragma unroll
                for (int mi = 0; mi < 2; mi++) {
                    mma_bf16(acc[mi][nt * 2],     ah[mi][0], ah[mi][1], ah[mi][2], ah[mi][3], h0, h1);
                    mma_bf16(acc[mi][nt * 2 + 1], ah[mi][0], ah[mi][1], ah[mi][2], ah[mi][3], h2, h3);
                    mma_bf16(acc[mi][nt * 2],     ah[mi][0], ah[mi][1], ah[mi][2], ah[mi][3], l0, l1);
                    mma_bf16(acc[mi][nt * 2 + 1], ah[mi][0], ah[mi][1], ah[mi][2], ah[mi][3], l2, l3);
                    mma_bf16(acc[mi][nt * 2],     al[mi][0], al[mi][1], al[mi][2], al[mi][3], h0, h1);
                    mma_bf16(acc[mi][nt * 2 + 1], al[mi][0], al[mi][1], al[mi][2], al[mi][3], h2, h3);
                }
            }
        }
        __syncthreads();
        if (c + 2 <= 3) g_load_w(c + 2, buf, tid, nbase, Whz, Wlz, sb);
    }

    #pragma unroll
    for (int mi = 0; mi < 2; mi++) {
        long row0 = mbase + wm + mi * 16 + (lane >> 2);
        #pragma unroll
        for (int n8 = 0; n8 < 8; n8++) {
            int col = nbase + wn + n8 * 8 + (lane & 3) * 2;
            float b0 = __ldg(&bias[col]);
            float b1 = __ldg(&bias[col + 1]);
            float2 o0, o1;
            o0.x = acc[mi][n8][0] + b0;
            o0.y = acc[mi][n8][1] + b1;
            o1.x = acc[mi][n8][2] + b0;
            o1.y = acc[mi][n8][3] + b1;
            *(float2*)&C[row0 * DIM + col] = o0;
            *(float2*)&C[(row0 + 8) * DIM + col] = o1;
        }
    }
}

// ---------------- attention v5: MLP-batched staging + 4-warp phase A ----------------
#define ASTR   68      // floats per row (16B aligned)
#define NBROWS 35      // base rows (halo 3)
#define NPROWS 24      // pooled rows: 16 (scale2) + 8 (scale4)
#define STOT   (3 * NBROWS * 16)   // 1680 float4 slots

__device__ __forceinline__ void scores_v(const float* __restrict__ qt,
                                         const float* __restrict__ kt,
                                         int lrow, int lk0,
                                         float* __restrict__ aout,
                                         int l0, int lq, int Ts)
{
    const float4* qp = (const float4*)(qt + lrow * ASTR);
    const float4* k0 = (const float4*)(kt + lk0 * ASTR);
    const float4* k1 = k0 + 17;
    const float4* k2 = k1 + 17;
    const float4* k3 = k2 + 17;
    float s0 = 0.f, s1 = 0.f, s2 = 0.f, s3 = 0.f;
    #pragma unroll
    for (int c = 0; c < 16; c++) {
        float4 q4 = qp[c];
        float4 a = k0[c], b = k1[c], d = k2[c], e = k3[c];
        s0 += q4.x * a.x + q4.y * a.y + q4.z * a.z + q4.w * a.w;
        s1 += q4.x * b.x + q4.y * b.y + q4.z * b.z + q4.w * b.w;
        s2 += q4.x * d.x + q4.y * d.y + q4.z * d.z + q4.w * d.w;
        s3 += q4.x * e.x + q4.y * e.y + q4.z * e.z + q4.w * e.w;
    }
    bool v0 = l0 < Ts, v1 = l0 + 1 < Ts, v2 = l0 + 2 < Ts, v3 = l0 + 3 < Ts;
    s0 = v0 ? s0 * 0.125f : 0.f;
    s1 = v1 ? s1 * 0.125f : 0.f;
    s2 = v2 ? s2 * 0.125f : 0.f;
    s3 = v3 ? s3 * 0.125f : 0.f;
    float mx = fmaxf(fmaxf(s0, s1), fmaxf(s2, s3));
    float e0 = expf(s0 - mx), e1 = expf(s1 - mx);
    float e2 = expf(s2 - mx), e3 = expf(s3 - mx);
    float inv = 1.0f / (e0 + e1 + e2 + e3);
    aout[0] = v0 ? e0 * inv : 0.f;
    aout[1] = v1 ? e1 * inv : 0.f;
    aout[2] = v2 ? e2 * inv : 0.f;
    aout[3] = v3 ? e3 * inv : 0.f;
    float wgt = 0.f;
    if (lq < Ts)
        wgt = (float)((TSEQ * (lq + 1) + Ts - 1) / Ts - (TSEQ * lq + Ts - 1) / Ts);
    aout[4] = wgt;
}

__device__ __forceinline__ void outrows_v(const float* __restrict__ vt,
                                          const float* __restrict__ awb,
                                          int r0, int r1, int voff, int lane,
                                          float& acc0, float& acc1)
{
    const float2* vbase = (const float2*)vt + lane;
    for (int rl = r0; rl < r1; rl++) {
        const float* e = awb + rl * 8;
        float wgt = e[4];
        if (wgt == 0.0f) continue;
        const float2* vp = vbase + (voff + (rl >> 2) * 4) * 34;
        float2 w0 = vp[0], w1 = vp[34], w2 = vp[68], w3 = vp[102];
        float a0 = e[0], a1 = e[1], a2 = e[2], a3 = e[3];
        float o0 = a0 * w0.x + a1 * w1.x + a2 * w2.x + a3 * w3.x;
        float o1 = a0 * w0.y + a1 * w1.y + a2 * w2.y + a3 * w3.y;
        float g0 = 0.5f * o0 * (1.0f + erff(o0 * 0.70710678118f));
        float g1 = 0.5f * o1 * (1.0f + erff(o1 * 0.70710678118f));
        acc0 += wgt * g0;
        acc1 += wgt * g1;
    }
}

__global__ __launch_bounds__(128) void attn5_kernel()
{
    extern __shared__ float smf[];
    float* bq_ = smf;                                   // base q [35][68]
    float* bk_ = bq_ + NBROWS * ASTR;
    float* bv_ = bk_ + NBROWS * ASTR;
    float* pq  = bv_ + NBROWS * ASTR;                   // pooled q [24][68]
    float* pk  = pq + NPROWS * ASTR;
    float* pv  = pk + NPROWS * ASTR;
    float* aw  = pv + NPROWS * ASTR;                    // [56][8]
    float* accw = aw + 56 * 8;                          // [4][64]

    const int tid = threadIdx.x;
    const int h  = blockIdx.x;
    const int bi = blockIdx.y;     // span 0..128 (128 = ragged tail)
    const int b  = blockIdx.z;
    const int sbase = bi * 32 - 3;
    const long gbase = (long)b * TSEQ * DIM + h * HD;

    const float* gq = g_q + gbase;
    const float* gk = g_k + gbase;
    const float* gv = g_v + gbase;

    // ---- staging with explicit MLP: two register batches of 7 ----
    {
        float4 tmp[7];
        #pragma unroll
        for (int i = 0; i < 7; i++) {
            int idx = tid + i * 128;
            int t = idx / (NBROWS * 16);
            int rem = idx - t * (NBROWS * 16);
            int r = rem >> 4, c4 = (rem & 15) * 4;
            int o = sbase + r;
            if (o < 0) o = -o;
            if (o >= TSEQ) o = 2 * TSEQ - 2 - o;
            const float* src = (t == 0 ? gq : t == 1 ? gk : gv) + (long)o * DIM + c4;
            tmp[i] = *(const float4*)src;
        }
        #pragma unroll
        for (int i = 0; i < 7; i++) {
            int idx = tid + i * 128;
            int t = idx / (NBROWS * 16);
            int rem = idx - t * (NBROWS * 16);
            int r = rem >> 4, c4 = (rem & 15) * 4;
            float* dst = (t == 0 ? bq_ : t == 1 ? bk_ : bv_) + r * ASTR + c4;
            *(float4*)dst = tmp[i];
        }
        #pragma unroll
        for (int i = 7; i < 14; i++) {
            int idx = tid + i * 128;
            if (idx < STOT) {
                int t = idx / (NBROWS * 16);
                int rem = idx - t * (NBROWS * 16);
                int r = rem >> 4, c4 = (rem & 15) * 4;
                int o = sbase + r;
                if (o < 0) o = -o;
                if (o >= TSEQ) o = 2 * TSEQ - 2 - o;
                const float* src = (t == 0 ? gq : t == 1 ? gk : gv) + (long)o * DIM + c4;
                tmp[i - 7] = *(const float4*)src;
            }
        }
        #pragma unroll
        for (int i = 7; i < 14; i++) {
            int idx = tid + i * 128;
            if (idx < STOT) {
                int t = idx / (NBROWS * 16);
                int rem = idx - t * (NBROWS * 16);
                int r = rem >> 4, c4 = (rem & 15) * 4;
                float* dst = (t == 0 ? bq_ : t == 1 ? bk_ : bv_) + r * ASTR + c4;
                *(float4*)dst = tmp[i - 7];
            }
        }
    }
    __syncthreads();

    // ---- pooling pass: rows 0-15 scale2 (base 2l+2,2l+3); 16-23 scale4 (base 4l+1..4l+4) ----
    for (int idx = tid; idx < 3 * NPROWS * 16; idx += 128) {
        int t = idx / (NPROWS * 16);
        int rem = idx - t * (NPROWS * 16);
        int r = rem >> 4;
        int c4 = (rem & 15) * 4;
        const float* bt = (t == 0 ? bq_ : t == 1 ? bk_ : bv_);
        float* pt = (t == 0 ? pq : t == 1 ? pk : pv);
        float4 o;
        if (r < 16) {
            const float4 a = *(const float4*)(bt + (2 * r + 2) * ASTR + c4);
            const float4 c = *(const float4*)(bt + (2 * r + 3) * ASTR + c4);
            o.x = 0.5f * (a.x + c.x); o.y = 0.5f * (a.y + c.y);
            o.z = 0.5f * (a.z + c.z); o.w = 0.5f * (a.w + c.w);
        } else {
            int rr = r - 16;
            const float4 a = *(const float4*)(bt + (4 * rr + 1) * ASTR + c4);
            const float4 c = *(const float4*)(bt + (4 * rr + 2) * ASTR + c4);
            const float4 d = *(const float4*)(bt + (4 * rr + 3) * ASTR + c4);
            const float4 e = *(const float4*)(bt + (4 * rr + 4) * ASTR + c4);
            o.x = 0.25f * (a.x + c.x + d.x + e.x);
            o.y = 0.25f * (a.y + c.y + d.y + e.y);
            o.z = 0.25f * (a.z + c.z + d.z + e.z);
            o.w = 0.25f * (a.w + c.w + d.w + e.w);
        }
        *(float4*)(pt + r * ASTR + c4) = o;
    }
    __syncthreads();

    const int warp = tid >> 5;
    const int lane = tid & 31;

    // ---- phase A across all 4 warps ----
    if (lane < 16) {
        if (warp < 2) {
            int j = warp * 16 + lane;           // s1 row 0..31
            scores_v(bq_, bk_, 3 + j, 3 + (j & ~3), aw + j * 8,
                     bi * 32 + (j & ~3), bi * 32 + j, TSEQ);
        } else if (warp == 2) {
            int j = lane;                        // s2 row 0..15
            scores_v(pq, pk, j, j & ~3, aw + (32 + j) * 8,
                     bi * 16 + (j & ~3), bi * 16 + j, 2049);
        } else if (lane < 8) {
            int j = lane;                        // s4 row 0..7
            scores_v(pq, pk, 16 + j, 16 + (j & ~3), aw + (48 + j) * 8,
                     bi * 8 + (j & ~3), bi * 8 + j, 1025);
        }
    }
    __syncthreads();

    // ---- phase B ----
    float acc0 = 0.f, acc1 = 0.f;
    if (warp == 0)      outrows_v(bv_, aw,          0, 16, 3,  lane, acc0, acc1);
    else if (warp == 2) outrows_v(bv_, aw,         16, 32, 3,  lane, acc0, acc1);
    else if (warp == 1) outrows_v(pv,  aw + 32 * 8, 0, 16, 0,  lane, acc0, acc1);
    else                outrows_v(pv,  aw + 48 * 8, 0,  8, 16, lane, acc0, acc1);

    *(float2*)&accw[warp * HD + 2 * lane] = make_float2(acc0, acc1);
    __syncthreads();

    if (tid < HD) {
        float s = accw[tid] + accw[HD + tid] + accw[2 * HD + tid] + accw[3 * HD + tid];
        atomicAdd(&g_acc[b * DIM + h * HD + tid], s);
    }
}

// ---------------- classifier ----------------
__global__ __launch_bounds__(256) void classifier_kernel(
    const float* __restrict__ Wp,  const float* __restrict__ bp,
    const float* __restrict__ Wc1, const float* __restrict__ bc1,
    const float* __restrict__ Wc2, const float* __restrict__ bc2,
    float* __restrict__ out)
{
    __shared__ float m[DIM], fm[DIM], hbuf[DIM];
    const int b = blockIdx.x;
    const int t = threadIdx.x;

    m[t] = g_acc[b * DIM + t] * (1.0f / (float)TSEQ);
    __syncthreads();

    float a = bp[t];
    for (int k = 0; k < DIM; k++) a += m[k] * Wp[k * DIM + t];
    fm[t] = a;
    __syncthreads();

    float a2 = bc1[t];
    for (int k = 0; k < DIM; k++) a2 += fm[k] * Wc1[k * DIM + t];
    hbuf[t] = fmaxf(a2, 0.0f);
    __syncthreads();

    if (t < 7) {
        float a3 = bc2[t];
        for (int k = 0; k < DIM; k++) a3 += hbuf[k] * Wc2[k * 7 + t];
        out[b * 7 + t] = a3;
    }
}

// ---------------- launch ----------------
extern "C" void kernel_launch(void* const* d_in, const int* in_sizes, int n_in,
                              void* d_out, int out_size)
{
    const float* x   = (const float*)d_in[0];
    const float* Wq  = (const float*)d_in[1];
    const float* bq  = (const float*)d_in[2];
    const float* Wk  = (const float*)d_in[3];
    const float* bk  = (const float*)d_in[4];
    const float* Wv  = (const float*)d_in[5];
    const float* bv  = (const float*)d_in[6];
    const float* Wp  = (const float*)d_in[7];
    const float* bp  = (const float*)d_in[8];
    const float* Wc1 = (const float*)d_in[9];
    const float* bc1 = (const float*)d_in[10];
    const float* Wc2 = (const float*)d_in[11];
    const float* bc2 = (const float*)d_in[12];
    float* out = (float*)d_out;

    const int asmem = (3 * NBROWS * ASTR + 3 * NPROWS * ASTR + 56 * 8 + 4 * HD) * (int)sizeof(float);
    cudaFuncSetAttribute(gemm_fused_kernel, cudaFuncAttributeMaxDynamicSharedMemorySize, GSMEM_BYTES);
    cudaFuncSetAttribute(attn5_kernel, cudaFuncAttributeMaxDynamicSharedMemorySize, asmem);

    zero_acc_kernel<<<(BATCH * DIM + 255) / 256, 256>>>();

    cvt_w_kernel<<<(3 * DIM * DIM / 4 + 255) / 256, 256>>>(Wq, Wk, Wv);

    gemm_fused_kernel<<<dim3(3, 2, MTOT / 128), 256, GSMEM_BYTES>>>(x, bq, bk, bv);

    attn5_kernel<<<dim3(4, 129, BATCH), 128, asmem>>>();

    classifier_kernel<<<BATCH, 256>>>(Wp, bp, Wc1, bc1, Wc2, bc2, out);
}